// round 8
// baseline (speedup 1.0000x reference)
#include <cuda_runtime.h>
#include <cuda_bf16.h>
#include <cstdint>
#include <math.h>

#define NN      2048
#define DIM     512
#define EDGE    8
#define GROWS   (EDGE * NN)
#define SLOTS   128          // padded CSR slots per gather row (17 sigma above mean nnz)
#define NSTEPS  5

// ---------------- device scratch (no allocation allowed) -------------------
__device__ __align__(256) float d_h [NN * DIM];
__device__ __align__(256) float d_z [NN * DIM];
__device__ __align__(256) __nv_bfloat16 d_hh [NN * DIM], d_hl [NN * DIM];
__device__ __align__(256) __nv_bfloat16 d_ah [NN * DIM], d_al [NN * DIM];
__device__ __align__(256) __nv_bfloat16 d_rhh[NN * DIM], d_rhl[NN * DIM];
__device__ __align__(256) __nv_bfloat16 d_Gh [GROWS * DIM], d_Gl [GROWS * DIM];
__device__ __align__(256) __nv_bfloat16 d_Bagg_h[DIM * 4096], d_Bagg_l[DIM * 4096]; // [n=512][k=4096]
__device__ __align__(256) __nv_bfloat16 d_Bzr_h[1024 * 1024], d_Bzr_l[1024 * 1024]; // [n=1024][k=1024]
__device__ __align__(256) __nv_bfloat16 d_Bh_h [DIM * 1024],  d_Bh_l [DIM * 1024];  // [n=512][k=1024]
__device__ int   d_cnt   [GROWS];
__device__ float d_cntf  [GROWS];
__device__ int   d_colidx_pad[GROWS * SLOTS];   // 8 MB

// ---------------- mma/ldmatrix/cp.async helpers (baseline PTX) -------------
__device__ __forceinline__ void ldsm4(uint32_t* r, uint32_t addr) {
    asm volatile("ldmatrix.sync.aligned.m8n8.x4.shared.b16 {%0,%1,%2,%3}, [%4];"
        : "=r"(r[0]), "=r"(r[1]), "=r"(r[2]), "=r"(r[3]) : "r"(addr));
}
__device__ __forceinline__ void mma16816(float* d, const uint32_t* a, const uint32_t* b) {
    asm volatile("mma.sync.aligned.m16n8k16.row.col.f32.bf16.bf16.f32 "
        "{%0,%1,%2,%3}, {%4,%5,%6,%7}, {%8,%9}, {%0,%1,%2,%3};"
        : "+f"(d[0]), "+f"(d[1]), "+f"(d[2]), "+f"(d[3])
        : "r"(a[0]), "r"(a[1]), "r"(a[2]), "r"(a[3]), "r"(b[0]), "r"(b[1]));
}
__device__ __forceinline__ void cpa16(uint32_t smaddr, const void* g) {
    asm volatile("cp.async.cg.shared.global [%0], [%1], 16;" :: "r"(smaddr), "l"(g));
}
#define CPA_COMMIT() asm volatile("cp.async.commit_group;")
#define CPA_WAIT1()  asm volatile("cp.async.wait_group 1;")
#define CPA_WAIT0()  asm volatile("cp.async.wait_group 0;")

__device__ __forceinline__ void store_hilo2(__nv_bfloat16* ph, __nv_bfloat16* pl,
                                            float v0, float v1) {
    __nv_bfloat16 h0 = __float2bfloat16(v0);
    __nv_bfloat16 h1 = __float2bfloat16(v1);
    __nv_bfloat16 l0 = __float2bfloat16(v0 - __bfloat162float(h0));
    __nv_bfloat16 l1 = __float2bfloat16(v1 - __bfloat162float(h1));
    *(__nv_bfloat162*)ph = __nv_bfloat162(h0, h1);
    *(__nv_bfloat162*)pl = __nv_bfloat162(l0, l1);
}

// ---------------- single-pass padded CSR build ------------------------------
// gather row g = e*2048 + n scans adjacency[n, e*2048 .. e*2048+2048)
__global__ void csr_build(const float* __restrict__ adj) {
    int warp = (blockIdx.x * blockDim.x + threadIdx.x) >> 5;
    int lane = threadIdx.x & 31;
    if (warp >= GROWS) return;
    int e = warp >> 11, n = warp & 2047;
    const float* base = adj + (size_t)n * 16384 + (size_t)e * 2048;
    int* dst = d_colidx_pad + (size_t)warp * SLOTS;
    int w = 0;
    for (int i0 = 0; i0 < 2048; i0 += 32) {
        float v = base[i0 + lane];
        unsigned b = __ballot_sync(0xffffffffu, v != 0.0f);
        if (v != 0.0f) {
            int pos = w + __popc(b & ((1u << lane) - 1u));
            if (pos < SLOTS) dst[pos] = i0 + lane;
        }
        w += __popc(b);
    }
    if (lane == 0) {
        d_cnt[warp] = (w < SLOTS) ? w : SLOTS;
        d_cntf[warp] = (float)w;
    }
}

// ---------------- init h + hi/lo -------------------------------------------
__global__ void init_h(const float* __restrict__ ann) {
    int idx = blockIdx.x * blockDim.x + threadIdx.x;
    if (idx >= NN * DIM) return;
    int n = idx >> 9, d = idx & 511;
    float v = (d < 256) ? ann[n * 256 + d] : 0.0f;
    d_h[idx] = v;
    __nv_bfloat16 h = __float2bfloat16(v);
    d_hh[idx] = h;
    d_hl[idx] = __float2bfloat16(v - __bfloat162float(h));
}

// ---------------- weight transpose+pack (all 14 jobs in one launch) --------
__global__ void packAll(const float* __restrict__ Wp, const float* __restrict__ Wz,
                        const float* __restrict__ Uz, const float* __restrict__ Wr,
                        const float* __restrict__ Ur, const float* __restrict__ Wh,
                        const float* __restrict__ Uh) {
    __shared__ float t[32][33];
    const int job = blockIdx.z;
    const float* src;
    __nv_bfloat16 *dh, *dl;
    int Kstride, nofs, kofs;
    if (job < 8) {
        src = Wp + (size_t)job * DIM * DIM;
        dh = d_Bagg_h; dl = d_Bagg_l; Kstride = 4096; nofs = 0; kofs = job * 512;
    } else if (job < 12) {
        dh = d_Bzr_h; dl = d_Bzr_l; Kstride = 1024;
        if (job == 8)       { src = Wz; nofs = 0;   kofs = 0;   }
        else if (job == 9)  { src = Uz; nofs = 0;   kofs = 512; }
        else if (job == 10) { src = Wr; nofs = 512; kofs = 0;   }
        else                { src = Ur; nofs = 512; kofs = 512; }
    } else {
        dh = d_Bh_h; dl = d_Bh_l; Kstride = 1024;
        if (job == 12) { src = Wh; nofs = 0; kofs = 0;   }
        else           { src = Uh; nofs = 0; kofs = 512; }
    }
    int k0 = blockIdx.x * 32, n0 = blockIdx.y * 32;
    int tx = threadIdx.x, ty = threadIdx.y;   // (32,8)
    #pragma unroll
    for (int j = 0; j < 32; j += 8)
        t[ty + j][tx] = src[(size_t)(k0 + ty + j) * DIM + n0 + tx];
    __syncthreads();
    #pragma unroll
    for (int j = 0; j < 32; j += 8) {
        float v = t[tx][ty + j];
        size_t o = (size_t)(nofs + n0 + ty + j) * Kstride + kofs + k0 + tx;
        __nv_bfloat16 h = __float2bfloat16(v);
        dh[o] = h;
        dl[o] = __float2bfloat16(v - __bfloat162float(h));
    }
}

// ---------------- gather v2: smem-resident h column-chunk -------------------
// grid (32 chunks, 4 rowblocks), 512 threads. smem: h[0:2048, c*16:(c+1)*16] = 128 KB.
// Warp processes a gather row: lanes 0-15 -> neighbor j, lanes 16-31 -> j+1,
// lane handles column (lane&15); combine halves via shfl_xor(16).
#define GATH_SMEM (2048 * 16 * 4)

__global__ void __launch_bounds__(512)
gather2() {
    extern __shared__ __align__(16) float hs[];
    const int tid = threadIdx.x, lane = tid & 31, warp = tid >> 5;
    const int c = blockIdx.x;                 // column chunk (16 floats)
    const int rowbase = blockIdx.y * 4096;
    const uint32_t smb = (uint32_t)__cvta_generic_to_shared(hs);

    // stage h[:, c*16 .. c*16+16) into smem
    for (int idx = tid; idx < 2048 * 4; idx += 512) {
        int node = idx >> 2, q = idx & 3;
        cpa16(smb + (uint32_t)(node * 16 + q * 4) * 4,
              d_h + (size_t)node * 512 + c * 16 + q * 4);
    }
    CPA_COMMIT();
    CPA_WAIT0();
    __syncthreads();

    const int half = lane >> 4;               // 0 or 1
    const int li = lane & 15;                 // column within chunk

    for (int g = rowbase + warp; g < rowbase + 4096; g += 16) {
        const int cnt = d_cnt[g];
        const int* idxp = d_colidx_pad + (size_t)g * SLOTS;
        float acc = 0.0f;
        #pragma unroll 4
        for (int j = 0; j < cnt; j += 2) {
            int jj = j + half;
            float v = 0.0f;
            if (jj < cnt) {
                int m = __ldg(idxp + jj);
                v = hs[m * 16 + li];
            }
            acc += v;
        }
        acc += __shfl_xor_sync(0xffffffffu, acc, 16);
        if (half == 0) {
            size_t o = (size_t)g * DIM + c * 16 + li;
            __nv_bfloat16 h = __float2bfloat16(acc);
            d_Gh[o] = h;
            d_Gl[o] = __float2bfloat16(acc - __bfloat162float(h));
        }
    }
}

// ---------------- warp-MMA GEMM: fused 3-product, 128x64 tile --------------
// MODE 0 (AGG): A = G (8 segs), B = Bagg [512][4096]; epi: += cnt*b_prop -> a hi/lo
// MODE 1 (ZR) : A = {a,h},      B = Bzr [1024][1024]; epi: z / r*h
// MODE 2 (H)  : A = {a,rh},     B = Bh  [512][1024];  epi: GRU combine
__device__ __forceinline__ const __nv_bfloat16* segA(int mode, bool lo, int seg) {
    if (mode == 0) return (lo ? d_Gl : d_Gh) + (size_t)seg * (NN * DIM);
    if (mode == 1) return seg ? (lo ? d_hl : d_hh) : (lo ? d_al : d_ah);
    return seg ? (lo ? d_rhl : d_rhh) : (lo ? d_al : d_ah);
}
__device__ __forceinline__ const __nv_bfloat16* segB(int mode, bool lo) {
    if (mode == 0) return lo ? d_Bagg_l : d_Bagg_h;
    if (mode == 1) return lo ? d_Bzr_l : d_Bzr_h;
    return lo ? d_Bh_l : d_Bh_h;
}

#define STAGES     3
#define STAGE_SZ   49152     // Ah 16K | Al 16K | Bh 8K | Bl 8K
#define SM_DYN     (STAGES * STAGE_SZ)   // 144 KB

template <int MODE>
__device__ __forceinline__ void load_tile_async(uint32_t stage_base, int t,
                                                int row0, int col0, int tid) {
    constexpr int BK = (MODE == 0) ? 4096 : 1024;
    int seg = t >> 3, kti = t & 7;
    const char* Abh = (const char*)(segA(MODE, false, seg) + (size_t)row0 * 512 + kti * 64);
    const char* Abl = (const char*)(segA(MODE, true,  seg) + (size_t)row0 * 512 + kti * 64);
    const char* Bbh = (const char*)(segB(MODE, false) + (size_t)col0 * BK + seg * 512 + kti * 64);
    const char* Bbl = (const char*)(segB(MODE, true)  + (size_t)col0 * BK + seg * 512 + kti * 64);
    #pragma unroll
    for (int i = 0; i < 4; i++) {
        int cc = tid + (i << 8);           // 0..1023  (A: 128 rows x 128B)
        int r = cc >> 3, kb = (cc & 7) << 4;
        int off = (r << 7) + kb;
        off ^= (off >> 3) & 0x70;
        cpa16(stage_base + off,         Abh + (size_t)r * 1024 + kb);
        cpa16(stage_base + 16384 + off, Abl + (size_t)r * 1024 + kb);
    }
    #pragma unroll
    for (int i = 0; i < 2; i++) {
        int cc = tid + (i << 8);           // 0..511   (B: 64 rows x 128B)
        int r = cc >> 3, kb = (cc & 7) << 4;
        int off = (r << 7) + kb;
        off ^= (off >> 3) & 0x70;
        cpa16(stage_base + 32768 + off, Bbh + (size_t)r * (BK * 2) + kb);
        cpa16(stage_base + 40960 + off, Bbl + (size_t)r * (BK * 2) + kb);
    }
}

template <int MODE>
__global__ void __launch_bounds__(256)
mma_gemm(const float* __restrict__ bias1, const float* __restrict__ bias2,
         float* __restrict__ outF) {
    extern __shared__ __align__(1024) char sm[];
    const int tid = threadIdx.x, lane = tid & 31, warp = tid >> 5;
    const int wm = warp >> 1, wn = warp & 1;     // 4 x 2 warps, warp tile 32x32
    const int row0 = blockIdx.y * 128, col0 = blockIdx.x * 64;
    constexpr int KT = ((MODE == 0) ? 4096 : 1024) / 64;
    const uint32_t smb = (uint32_t)__cvta_generic_to_shared(sm);

    float acc[2][4][4];
    #pragma unroll
    for (int i = 0; i < 2; i++)
        #pragma unroll
        for (int j = 0; j < 4; j++)
            #pragma unroll
            for (int q = 0; q < 4; q++) acc[i][j][q] = 0.0f;

    // ldmatrix lane constants
    const uint32_t xmask = (uint32_t)(lane & 7) << 4;
    const int arow = lane & 15;
    const uint32_t ach0 = (uint32_t)(lane >> 4) << 4;
    const int brow = (lane & 7) + ((lane >> 4) << 3);
    const uint32_t bch0 = (uint32_t)((lane >> 3) & 1) << 4;

    // prologue
    #pragma unroll
    for (int p = 0; p < STAGES - 1; p++) {
        load_tile_async<MODE>(smb + p * STAGE_SZ, p, row0, col0, tid);
        CPA_COMMIT();
    }

    int buf = 0;
    for (int t = 0; t < KT; t++) {
        CPA_WAIT1();
        __syncthreads();

        const int nt = t + STAGES - 1;
        if (nt < KT) {
            int nbuf = buf + STAGES - 1;
            if (nbuf >= STAGES) nbuf -= STAGES;
            load_tile_async<MODE>(smb + nbuf * STAGE_SZ, nt, row0, col0, tid);
        }
        CPA_COMMIT();

        const uint32_t S0 = smb + buf * STAGE_SZ;
        const uint32_t aAddr0 = S0 + (uint32_t)(wm * 32 + arow) * 128;
        const uint32_t aAddr1 = aAddr0 + 2048;
        const uint32_t bAddr0 = S0 + 32768 + (uint32_t)(wn * 32 + brow) * 128;
        const uint32_t bAddr1 = bAddr0 + 2048;

        #pragma unroll
        for (int k16 = 0; k16 < 4; k16++) {
            uint32_t ah[2][4], al[2][4], bh[2][4], bl[2][4];
            const uint32_t ak = (ach0 + k16 * 32) ^ xmask;
            const uint32_t bk = (bch0 + k16 * 32) ^ xmask;
            ldsm4(ah[0], aAddr0 + ak);
            ldsm4(ah[1], aAddr1 + ak);
            ldsm4(al[0], aAddr0 + 16384 + ak);
            ldsm4(al[1], aAddr1 + 16384 + ak);
            ldsm4(bh[0], bAddr0 + bk);
            ldsm4(bh[1], bAddr1 + bk);
            ldsm4(bl[0], bAddr0 + 8192 + bk);
            ldsm4(bl[1], bAddr1 + 8192 + bk);
            #pragma unroll
            for (int i = 0; i < 2; i++) {
                #pragma unroll
                for (int j = 0; j < 4; j++) {
                    const uint32_t* bfh = &bh[j >> 1][(j & 1) * 2];
                    const uint32_t* bfl = &bl[j >> 1][(j & 1) * 2];
                    mma16816(acc[i][j], ah[i], bfh);
                    mma16816(acc[i][j], ah[i], bfl);
                    mma16816(acc[i][j], al[i], bfh);
                }
            }
        }

        if (++buf == STAGES) buf = 0;
    }

    // ---------------- epilogue ----------------
    #pragma unroll
    for (int i = 0; i < 2; i++) {
        #pragma unroll
        for (int hf = 0; hf < 2; hf++) {
            const int m = row0 + wm * 32 + i * 16 + (lane >> 2) + hf * 8;
            float cf[EDGE];
            if (MODE == 0) {
                #pragma unroll
                for (int e = 0; e < EDGE; e++) cf[e] = d_cntf[e * NN + m];
            }
            #pragma unroll
            for (int j = 0; j < 4; j++) {
                const int c = col0 + wn * 32 + j * 8 + (lane & 3) * 2;
                float v0 = acc[i][j][hf * 2 + 0];
                float v1 = acc[i][j][hf * 2 + 1];

                if (MODE == 0) {
                    #pragma unroll
                    for (int e = 0; e < EDGE; e++) {
                        v0 = fmaf(cf[e], __ldg(bias1 + e * DIM + c), v0);
                        v1 = fmaf(cf[e], __ldg(bias1 + e * DIM + c + 1), v1);
                    }
                    size_t o = (size_t)m * DIM + c;
                    store_hilo2(d_ah + o, d_al + o, v0, v1);
                } else if (MODE == 1) {
                    if (c < DIM) {
                        v0 = 1.0f / (1.0f + __expf(-(v0 + __ldg(bias1 + c))));
                        v1 = 1.0f / (1.0f + __expf(-(v1 + __ldg(bias1 + c + 1))));
                        *(float2*)(d_z + (size_t)m * DIM + c) = make_float2(v0, v1);
                    } else {
                        const int c2 = c - DIM;
                        size_t o = (size_t)m * DIM + c2;
                        float r0 = 1.0f / (1.0f + __expf(-(v0 + __ldg(bias2 + c2))));
                        float r1 = 1.0f / (1.0f + __expf(-(v1 + __ldg(bias2 + c2 + 1))));
                        float2 hv = *(const float2*)(d_h + o);
                        store_hilo2(d_rhh + o, d_rhl + o, r0 * hv.x, r1 * hv.y);
                    }
                } else {
                    size_t o = (size_t)m * DIM + c;
                    float ht0 = tanhf(v0 + __ldg(bias1 + c));
                    float ht1 = tanhf(v1 + __ldg(bias1 + c + 1));
                    float2 hv = *(const float2*)(d_h + o);
                    float2 zv = *(const float2*)(d_z + o);
                    float n0 = hv.x + zv.x * (ht0 - hv.x);
                    float n1 = hv.y + zv.y * (ht1 - hv.y);
                    float* dst = outF ? outF : d_h;
                    *(float2*)(dst + o) = make_float2(n0, n1);
                    store_hilo2(d_hh + o, d_hl + o, n0, n1);
                }
            }
        }
    }
}

// ---------------- launch ----------------------------------------------------
extern "C" void kernel_launch(void* const* d_in, const int* in_sizes, int n_in,
                              void* d_out, int out_size) {
    const float* adj = (const float*)d_in[0];
    const float* ann = (const float*)d_in[1];
    const float* Wp  = (const float*)d_in[2];
    const float* bp  = (const float*)d_in[3];
    const float* Wz  = (const float*)d_in[4];
    const float* Uz  = (const float*)d_in[5];
    const float* bz  = (const float*)d_in[6];
    const float* Wr  = (const float*)d_in[7];
    const float* Ur  = (const float*)d_in[8];
    const float* br  = (const float*)d_in[9];
    const float* Wh  = (const float*)d_in[10];
    const float* Uh  = (const float*)d_in[11];
    const float* bh  = (const float*)d_in[12];
    float* out = (float*)d_out;

    cudaFuncSetAttribute(mma_gemm<0>, cudaFuncAttributeMaxDynamicSharedMemorySize, SM_DYN);
    cudaFuncSetAttribute(mma_gemm<1>, cudaFuncAttributeMaxDynamicSharedMemorySize, SM_DYN);
    cudaFuncSetAttribute(mma_gemm<2>, cudaFuncAttributeMaxDynamicSharedMemorySize, SM_DYN);
    cudaFuncSetAttribute(gather2,     cudaFuncAttributeMaxDynamicSharedMemorySize, GATH_SMEM);

    csr_build<<<GROWS / 8, 256>>>(adj);
    init_h<<<(NN * DIM) / 256, 256>>>(ann);
    packAll<<<dim3(16, 16, 14), dim3(32, 8)>>>(Wp, Wz, Uz, Wr, Ur, Wh, Uh);

    dim3 gAgg(8, 16), gZr(16, 16), gH(8, 16);
    for (int step = 0; step < NSTEPS; step++) {
        gather2<<<dim3(32, 4), 512, GATH_SMEM>>>();
        mma_gemm<0><<<gAgg, 256, SM_DYN>>>(bp, nullptr, nullptr);
        mma_gemm<1><<<gZr,  256, SM_DYN>>>(bz, br, nullptr);
        mma_gemm<2><<<gH,   256, SM_DYN>>>(bh, nullptr,
                                           (step == NSTEPS - 1) ? out : nullptr);
    }
}

// round 9
// speedup vs baseline: 2.3431x; 2.3431x over previous
#include <cuda_runtime.h>
#include <cuda_bf16.h>
#include <cstdint>
#include <math.h>

#define NN      2048
#define DIM     512
#define EDGE    8
#define GROWS   (EDGE * NN)
#define SLOTS   128          // padded CSR slots per row (mean nnz 30.7, sigma ~5.5)
#define NSTEPS  5

// ---------------- device scratch (no allocation allowed) -------------------
__device__ __align__(256) float d_h [NN * DIM];
__device__ __align__(256) float d_z [NN * DIM];
__device__ __align__(256) __nv_bfloat16 d_hh [NN * DIM], d_hl [NN * DIM];
__device__ __align__(256) __nv_bfloat16 d_ah [NN * DIM], d_al [NN * DIM];
__device__ __align__(256) __nv_bfloat16 d_rhh[NN * DIM], d_rhl[NN * DIM];
__device__ __align__(256) __nv_bfloat16 d_Gh [GROWS * DIM], d_Gl [GROWS * DIM];
__device__ __align__(256) __nv_bfloat16 d_Bagg_h[DIM * 4096], d_Bagg_l[DIM * 4096]; // [n=512][k=4096]
__device__ __align__(256) __nv_bfloat16 d_Bzr_h[1024 * 1024], d_Bzr_l[1024 * 1024]; // [n=1024][k=1024]
__device__ __align__(256) __nv_bfloat16 d_Bh_h [DIM * 1024],  d_Bh_l [DIM * 1024];  // [n=512][k=1024]
__device__ int   d_cnt   [GROWS];
__device__ float d_cntf  [GROWS];
__device__ int   d_colidx_pad[GROWS * SLOTS];   // 8 MB

// ---------------- mma/ldmatrix/cp.async helpers (baseline PTX) -------------
__device__ __forceinline__ void ldsm4(uint32_t* r, uint32_t addr) {
    asm volatile("ldmatrix.sync.aligned.m8n8.x4.shared.b16 {%0,%1,%2,%3}, [%4];"
        : "=r"(r[0]), "=r"(r[1]), "=r"(r[2]), "=r"(r[3]) : "r"(addr));
}
__device__ __forceinline__ void mma16816(float* d, const uint32_t* a, const uint32_t* b) {
    asm volatile("mma.sync.aligned.m16n8k16.row.col.f32.bf16.bf16.f32 "
        "{%0,%1,%2,%3}, {%4,%5,%6,%7}, {%8,%9}, {%0,%1,%2,%3};"
        : "+f"(d[0]), "+f"(d[1]), "+f"(d[2]), "+f"(d[3])
        : "r"(a[0]), "r"(a[1]), "r"(a[2]), "r"(a[3]), "r"(b[0]), "r"(b[1]));
}
__device__ __forceinline__ void cpa16(uint32_t smaddr, const void* g) {
    asm volatile("cp.async.cg.shared.global [%0], [%1], 16;" :: "r"(smaddr), "l"(g));
}
#define CPA_COMMIT() asm volatile("cp.async.commit_group;")
#define CPA_WAIT1()  asm volatile("cp.async.wait_group 1;")

__device__ __forceinline__ void store_hilo2(__nv_bfloat16* ph, __nv_bfloat16* pl,
                                            float v0, float v1) {
    __nv_bfloat16 h0 = __float2bfloat16(v0);
    __nv_bfloat16 h1 = __float2bfloat16(v1);
    __nv_bfloat16 l0 = __float2bfloat16(v0 - __bfloat162float(h0));
    __nv_bfloat16 l1 = __float2bfloat16(v1 - __bfloat162float(h1));
    *(__nv_bfloat162*)ph = __nv_bfloat162(h0, h1);
    *(__nv_bfloat162*)pl = __nv_bfloat162(l0, l1);
}

// ---------------- single-pass padded CSR build ------------------------------
__global__ void csr_build(const float* __restrict__ adj) {
    int warp = (blockIdx.x * blockDim.x + threadIdx.x) >> 5;
    int lane = threadIdx.x & 31;
    if (warp >= GROWS) return;
    int e = warp >> 11, n = warp & 2047;
    const float* base = adj + (size_t)n * 16384 + (size_t)e * 2048;
    int* dst = d_colidx_pad + (size_t)warp * SLOTS;
    int w = 0;
    for (int i0 = 0; i0 < 2048; i0 += 32) {
        float v = base[i0 + lane];
        unsigned b = __ballot_sync(0xffffffffu, v != 0.0f);
        if (v != 0.0f) {
            int pos = w + __popc(b & ((1u << lane) - 1u));
            if (pos < SLOTS) dst[pos] = i0 + lane;
        }
        w += __popc(b);
    }
    if (lane == 0) {
        d_cnt[warp] = (w < SLOTS) ? w : SLOTS;
        d_cntf[warp] = (float)w;
    }
}

// ---------------- init h + hi/lo -------------------------------------------
__global__ void init_h(const float* __restrict__ ann) {
    int idx = blockIdx.x * blockDim.x + threadIdx.x;
    if (idx >= NN * DIM) return;
    int n = idx >> 9, d = idx & 511;
    float v = (d < 256) ? ann[n * 256 + d] : 0.0f;
    d_h[idx] = v;
    __nv_bfloat16 h = __float2bfloat16(v);
    d_hh[idx] = h;
    d_hl[idx] = __float2bfloat16(v - __bfloat162float(h));
}

// ---------------- weight transpose+pack (all 14 jobs in one launch) --------
__global__ void packAll(const float* __restrict__ Wp, const float* __restrict__ Wz,
                        const float* __restrict__ Uz, const float* __restrict__ Wr,
                        const float* __restrict__ Ur, const float* __restrict__ Wh,
                        const float* __restrict__ Uh) {
    __shared__ float t[32][33];
    const int job = blockIdx.z;
    const float* src;
    __nv_bfloat16 *dh, *dl;
    int Kstride, nofs, kofs;
    if (job < 8) {
        src = Wp + (size_t)job * DIM * DIM;
        dh = d_Bagg_h; dl = d_Bagg_l; Kstride = 4096; nofs = 0; kofs = job * 512;
    } else if (job < 12) {
        dh = d_Bzr_h; dl = d_Bzr_l; Kstride = 1024;
        if (job == 8)       { src = Wz; nofs = 0;   kofs = 0;   }
        else if (job == 9)  { src = Uz; nofs = 0;   kofs = 512; }
        else if (job == 10) { src = Wr; nofs = 512; kofs = 0;   }
        else                { src = Ur; nofs = 512; kofs = 512; }
    } else {
        dh = d_Bh_h; dl = d_Bh_l; Kstride = 1024;
        if (job == 12) { src = Wh; nofs = 0; kofs = 0;   }
        else           { src = Uh; nofs = 0; kofs = 512; }
    }
    int k0 = blockIdx.x * 32, n0 = blockIdx.y * 32;
    int tx = threadIdx.x, ty = threadIdx.y;   // (32,8)
    #pragma unroll
    for (int j = 0; j < 32; j += 8)
        t[ty + j][tx] = src[(size_t)(k0 + ty + j) * DIM + n0 + tx];
    __syncthreads();
    #pragma unroll
    for (int j = 0; j < 32; j += 8) {
        float v = t[tx][ty + j];
        size_t o = (size_t)(nofs + n0 + ty + j) * Kstride + kofs + k0 + tx;
        __nv_bfloat16 h = __float2bfloat16(v);
        dh[o] = h;
        dl[o] = __float2bfloat16(v - __bfloat162float(h));
    }
}

// ---------------- gather (L2 path, proven): G[g,:] = sum h[col,:] ----------
__global__ void gather_k() {
    int g = blockIdx.x;
    int c = threadIdx.x;
    const int* idxp = d_colidx_pad + (size_t)g * SLOTS;
    const int cnt = d_cnt[g];
    const float4* hp = (const float4*)d_h;
    float4 acc = make_float4(0.f, 0.f, 0.f, 0.f);
    int j = 0;
    for (; j + 1 < cnt; j += 2) {
        int m0 = __ldg(idxp + j);
        int m1 = __ldg(idxp + j + 1);
        float4 v0 = hp[m0 * 128 + c];
        float4 v1 = hp[m1 * 128 + c];
        acc.x += v0.x; acc.y += v0.y; acc.z += v0.z; acc.w += v0.w;
        acc.x += v1.x; acc.y += v1.y; acc.z += v1.z; acc.w += v1.w;
    }
    if (j < cnt) {
        int m = __ldg(idxp + j);
        float4 v = hp[m * 128 + c];
        acc.x += v.x; acc.y += v.y; acc.z += v.z; acc.w += v.w;
    }
    size_t o = (size_t)g * DIM + c * 4;
    store_hilo2(d_Gh + o,     d_Gl + o,     acc.x, acc.y);
    store_hilo2(d_Gh + o + 2, d_Gl + o + 2, acc.z, acc.w);
}

// ---------------- warp-MMA GEMM: fused 3-product ----------------------------
// MODE 0 (AGG): 128x64 tile; MODE 1 (ZR): 128x128 tile; MODE 2 (H): 128x64.
__device__ __forceinline__ const __nv_bfloat16* segA(int mode, bool lo, int seg) {
    if (mode == 0) return (lo ? d_Gl : d_Gh) + (size_t)seg * (NN * DIM);
    if (mode == 1) return seg ? (lo ? d_hl : d_hh) : (lo ? d_al : d_ah);
    return seg ? (lo ? d_rhl : d_rhh) : (lo ? d_al : d_ah);
}
__device__ __forceinline__ const __nv_bfloat16* segB(int mode, bool lo) {
    if (mode == 0) return lo ? d_Bagg_l : d_Bagg_h;
    if (mode == 1) return lo ? d_Bzr_l : d_Bzr_h;
    return lo ? d_Bh_l : d_Bh_h;
}

#define STAGES 3

template <int MODE>
__device__ __forceinline__ void load_tile_async(uint32_t stage_base, int t,
                                                int row0, int col0, int tid) {
    constexpr bool W = (MODE == 1);
    constexpr int BK = (MODE == 0) ? 4096 : 1024;
    constexpr int BOFF = 32768;
    constexpr int BSZ  = W ? 16384 : 8192;
    int seg = t >> 3, kti = t & 7;
    const char* Abh = (const char*)(segA(MODE, false, seg) + (size_t)row0 * 512 + kti * 64);
    const char* Abl = (const char*)(segA(MODE, true,  seg) + (size_t)row0 * 512 + kti * 64);
    const char* Bbh = (const char*)(segB(MODE, false) + (size_t)col0 * BK + seg * 512 + kti * 64);
    const char* Bbl = (const char*)(segB(MODE, true)  + (size_t)col0 * BK + seg * 512 + kti * 64);
    #pragma unroll
    for (int i = 0; i < 4; i++) {           // A: 128 rows x 128B
        int cc = tid + (i << 8);
        int r = cc >> 3, kb = (cc & 7) << 4;
        int off = (r << 7) + kb;
        off ^= (off >> 3) & 0x70;
        cpa16(stage_base + off,         Abh + (size_t)r * 1024 + kb);
        cpa16(stage_base + 16384 + off, Abl + (size_t)r * 1024 + kb);
    }
    #pragma unroll
    for (int i = 0; i < (W ? 4 : 2); i++) { // B: (W?128:64) rows x 128B
        int cc = tid + (i << 8);
        int r = cc >> 3, kb = (cc & 7) << 4;
        int off = (r << 7) + kb;
        off ^= (off >> 3) & 0x70;
        cpa16(stage_base + BOFF + off,       Bbh + (size_t)r * (BK * 2) + kb);
        cpa16(stage_base + BOFF + BSZ + off, Bbl + (size_t)r * (BK * 2) + kb);
    }
}

template <int MODE>
__global__ void __launch_bounds__(256)
mma_gemm(const float* __restrict__ bias1, const float* __restrict__ bias2,
         float* __restrict__ outF) {
    extern __shared__ __align__(1024) char sm[];
    constexpr bool W = (MODE == 1);
    constexpr int MI = W ? 4 : 2;            // A fragments per warp
    constexpr int BSZ = W ? 16384 : 8192;
    constexpr int STAGE_SZ = 32768 + 2 * BSZ;
    constexpr int KT = ((MODE == 0) ? 4096 : 1024) / 64;
    const int tid = threadIdx.x, lane = tid & 31, warp = tid >> 5;
    const int wm = W ? (warp >> 2) : (warp >> 1);
    const int wn = W ? (warp & 3) : (warp & 1);
    const int wmext = W ? 64 : 32;
    const int row0 = blockIdx.y * 128, col0 = blockIdx.x * (W ? 128 : 64);
    const uint32_t smb = (uint32_t)__cvta_generic_to_shared(sm);

    float acc[MI][4][4];
    #pragma unroll
    for (int i = 0; i < MI; i++)
        #pragma unroll
        for (int j = 0; j < 4; j++)
            #pragma unroll
            for (int q = 0; q < 4; q++) acc[i][j][q] = 0.0f;

    const uint32_t xmask = (uint32_t)(lane & 7) << 4;
    const int arow = lane & 15;
    const uint32_t ach0 = (uint32_t)(lane >> 4) << 4;
    const int brow = (lane & 7) + ((lane >> 4) << 3);
    const uint32_t bch0 = (uint32_t)((lane >> 3) & 1) << 4;

    #pragma unroll
    for (int p = 0; p < STAGES - 1; p++) {
        load_tile_async<MODE>(smb + p * STAGE_SZ, p, row0, col0, tid);
        CPA_COMMIT();
    }

    int buf = 0;
    for (int t = 0; t < KT; t++) {
        CPA_WAIT1();
        __syncthreads();

        const int nt = t + STAGES - 1;
        if (nt < KT) {
            int nbuf = buf + STAGES - 1;
            if (nbuf >= STAGES) nbuf -= STAGES;
            load_tile_async<MODE>(smb + nbuf * STAGE_SZ, nt, row0, col0, tid);
        }
        CPA_COMMIT();

        const uint32_t S0 = smb + buf * STAGE_SZ;
        const uint32_t aAddr = S0 + (uint32_t)(wm * wmext + arow) * 128;
        const uint32_t bAddr0 = S0 + 32768 + (uint32_t)(wn * 32 + brow) * 128;
        const uint32_t bAddr1 = bAddr0 + 2048;

        #pragma unroll
        for (int k16 = 0; k16 < 4; k16++) {
            uint32_t ah[MI][4], al[MI][4], bh[2][4], bl[2][4];
            const uint32_t ak = (ach0 + k16 * 32) ^ xmask;
            const uint32_t bk = (bch0 + k16 * 32) ^ xmask;
            #pragma unroll
            for (int i = 0; i < MI; i++) {
                ldsm4(ah[i], aAddr + i * 2048 + ak);
                ldsm4(al[i], aAddr + 16384 + i * 2048 + ak);
            }
            ldsm4(bh[0], bAddr0 + bk);
            ldsm4(bh[1], bAddr1 + bk);
            ldsm4(bl[0], bAddr0 + BSZ + bk);
            ldsm4(bl[1], bAddr1 + BSZ + bk);
            #pragma unroll
            for (int i = 0; i < MI; i++) {
                #pragma unroll
                for (int j = 0; j < 4; j++) {
                    const uint32_t* bfh = &bh[j >> 1][(j & 1) * 2];
                    const uint32_t* bfl = &bl[j >> 1][(j & 1) * 2];
                    mma16816(acc[i][j], ah[i], bfh);
                    mma16816(acc[i][j], ah[i], bfl);
                    mma16816(acc[i][j], al[i], bfh);
                }
            }
        }

        if (++buf == STAGES) buf = 0;
    }

    // ---------------- epilogue ----------------
    #pragma unroll
    for (int i = 0; i < MI; i++) {
        #pragma unroll
        for (int hf = 0; hf < 2; hf++) {
            const int m = row0 + wm * wmext + i * 16 + (lane >> 2) + hf * 8;
            float cf[EDGE];
            if (MODE == 0) {
                #pragma unroll
                for (int e = 0; e < EDGE; e++) cf[e] = d_cntf[e * NN + m];
            }
            #pragma unroll
            for (int j = 0; j < 4; j++) {
                const int c = col0 + wn * 32 + j * 8 + (lane & 3) * 2;
                float v0 = acc[i][j][hf * 2 + 0];
                float v1 = acc[i][j][hf * 2 + 1];

                if (MODE == 0) {
                    #pragma unroll
                    for (int e = 0; e < EDGE; e++) {
                        v0 = fmaf(cf[e], __ldg(bias1 + e * DIM + c), v0);
                        v1 = fmaf(cf[e], __ldg(bias1 + e * DIM + c + 1), v1);
                    }
                    size_t o = (size_t)m * DIM + c;
                    store_hilo2(d_ah + o, d_al + o, v0, v1);
                } else if (MODE == 1) {
                    if (c < DIM) {
                        v0 = 1.0f / (1.0f + __expf(-(v0 + __ldg(bias1 + c))));
                        v1 = 1.0f / (1.0f + __expf(-(v1 + __ldg(bias1 + c + 1))));
                        *(float2*)(d_z + (size_t)m * DIM + c) = make_float2(v0, v1);
                    } else {
                        const int c2 = c - DIM;
                        size_t o = (size_t)m * DIM + c2;
                        float r0 = 1.0f / (1.0f + __expf(-(v0 + __ldg(bias2 + c2))));
                        float r1 = 1.0f / (1.0f + __expf(-(v1 + __ldg(bias2 + c2 + 1))));
                        float2 hv = *(const float2*)(d_h + o);
                        store_hilo2(d_rhh + o, d_rhl + o, r0 * hv.x, r1 * hv.y);
                    }
                } else {
                    size_t o = (size_t)m * DIM + c;
                    float ht0 = tanhf(v0 + __ldg(bias1 + c));
                    float ht1 = tanhf(v1 + __ldg(bias1 + c + 1));
                    float2 hv = *(const float2*)(d_h + o);
                    float2 zv = *(const float2*)(d_z + o);
                    float n0 = hv.x + zv.x * (ht0 - hv.x);
                    float n1 = hv.y + zv.y * (ht1 - hv.y);
                    float* dst = outF ? outF : d_h;
                    *(float2*)(dst + o) = make_float2(n0, n1);
                    store_hilo2(d_hh + o, d_hl + o, n0, n1);
                }
            }
        }
    }
}

// ---------------- launch ----------------------------------------------------
extern "C" void kernel_launch(void* const* d_in, const int* in_sizes, int n_in,
                              void* d_out, int out_size) {
    const float* adj = (const float*)d_in[0];
    const float* ann = (const float*)d_in[1];
    const float* Wp  = (const float*)d_in[2];
    const float* bp  = (const float*)d_in[3];
    const float* Wz  = (const float*)d_in[4];
    const float* Uz  = (const float*)d_in[5];
    const float* bz  = (const float*)d_in[6];
    const float* Wr  = (const float*)d_in[7];
    const float* Ur  = (const float*)d_in[8];
    const float* br  = (const float*)d_in[9];
    const float* Wh  = (const float*)d_in[10];
    const float* Uh  = (const float*)d_in[11];
    const float* bh  = (const float*)d_in[12];
    float* out = (float*)d_out;

    const int smN = STAGES * (32768 + 2 * 8192);    // 144 KB (MODE 0/2)
    const int smW = STAGES * (32768 + 2 * 16384);   // 192 KB (MODE 1)
    cudaFuncSetAttribute(mma_gemm<0>, cudaFuncAttributeMaxDynamicSharedMemorySize, smN);
    cudaFuncSetAttribute(mma_gemm<1>, cudaFuncAttributeMaxDynamicSharedMemorySize, smW);
    cudaFuncSetAttribute(mma_gemm<2>, cudaFuncAttributeMaxDynamicSharedMemorySize, smN);

    csr_build<<<GROWS / 8, 256>>>(adj);
    init_h<<<(NN * DIM) / 256, 256>>>(ann);
    packAll<<<dim3(16, 16, 14), dim3(32, 8)>>>(Wp, Wz, Uz, Wr, Ur, Wh, Uh);

    dim3 gAgg(8, 16), gZr(8, 16), gH(8, 16);
    for (int step = 0; step < NSTEPS; step++) {
        gather_k<<<GROWS, 128>>>();
        mma_gemm<0><<<gAgg, 256, smN>>>(bp, nullptr, nullptr);
        mma_gemm<1><<<gZr,  256, smW>>>(bz, br, nullptr);
        mma_gemm<2><<<gH,   256, smN>>>(bh, nullptr,
                                        (step == NSTEPS - 1) ? out : nullptr);
    }
}